// round 5
// baseline (speedup 1.0000x reference)
#include <cuda_runtime.h>
#include <cstdint>

// out[b,m] = dot(inputs[b,m,:], W[m,:]) + bias[m]
// B=1024, M=2048, I=128 (32 float4 per row).
//
// 8 rows per warp, 8 lanes per row-pair slot. lane = 8*g + sub:
//   g handles rows base+g and base+g+4; sub indexes 4 float4 per row.
// Each lane front-batches 16 loads (8 x streaming + 8 W L2-resident) -> MLP=16.
// One 3-step butterfly reduces both outputs (two regs through same shuffles).

static constexpr int M_DIM = 2048;
static constexpr long long TOTAL = 1024LL * 2048LL;  // B*M outputs (divisible by 8)

__device__ __forceinline__ float dot4(const float4 a, const float4 b) {
    float s = a.x * b.x;
    s = fmaf(a.y, b.y, s);
    s = fmaf(a.z, b.z, s);
    s = fmaf(a.w, b.w, s);
    return s;
}

__global__ __launch_bounds__(256, 3)
void rowdot_kernel(const float4* __restrict__ inp,   // [B*M, 32] float4
                   const float4* __restrict__ W,     // [M, 32] float4
                   const float*  __restrict__ bias,  // [M]
                   float* __restrict__ out)          // [B*M]
{
    const int lane = threadIdx.x & 31;
    const long long warp = (long long)blockIdx.x * 8 + (threadIdx.x >> 5);

    const int g   = lane >> 3;   // output slot 0..3
    const int sub = lane & 7;    // position within row (4 float4 apart)

    const long long base = warp * 8;
    const long long rowA = base + g;        // rows base..base+3
    const long long rowB = base + g + 4;    // rows base+4..base+7
    // base is 8-aligned and M=2048 divisible by 8 -> rowA/rowB share the batch.
    const int mA = (int)(rowA & (M_DIM - 1));
    const int mB = mA + 4;

    const float4* __restrict__ xa = inp + rowA * 32 + sub;
    const float4* __restrict__ xb = inp + rowB * 32 + sub;
    const float4* __restrict__ wa = W   + (long long)mA * 32 + sub;
    const float4* __restrict__ wb = W   + (long long)mB * 32 + sub;

    // Front-batch all 16 loads: x first (DRAM, longest latency), then W (L2).
    float4 a0 = __ldcs(xa + 0);
    float4 a1 = __ldcs(xa + 8);
    float4 a2 = __ldcs(xa + 16);
    float4 a3 = __ldcs(xa + 24);
    float4 b0 = __ldcs(xb + 0);
    float4 b1 = __ldcs(xb + 8);
    float4 b2 = __ldcs(xb + 16);
    float4 b3 = __ldcs(xb + 24);
    float4 u0 = __ldg(wa + 0);
    float4 u1 = __ldg(wa + 8);
    float4 u2 = __ldg(wa + 16);
    float4 u3 = __ldg(wa + 24);
    float4 v0 = __ldg(wb + 0);
    float4 v1 = __ldg(wb + 8);
    float4 v2 = __ldg(wb + 16);
    float4 v3 = __ldg(wb + 24);

    // Two accumulator chains per output, merged before the shuffle.
    float sA0 = dot4(a0, u0) + dot4(a2, u2);
    float sA1 = dot4(a1, u1) + dot4(a3, u3);
    float sB0 = dot4(b0, v0) + dot4(b2, v2);
    float sB1 = dot4(b1, v1) + dot4(b3, v3);
    float sA = sA0 + sA1;
    float sB = sB0 + sB1;

    // Butterfly within each 8-lane group: both outputs ride the same steps.
    sA += __shfl_xor_sync(0xFFFFFFFFu, sA, 4);
    sB += __shfl_xor_sync(0xFFFFFFFFu, sB, 4);
    sA += __shfl_xor_sync(0xFFFFFFFFu, sA, 2);
    sB += __shfl_xor_sync(0xFFFFFFFFu, sB, 2);
    sA += __shfl_xor_sync(0xFFFFFFFFu, sA, 1);
    sB += __shfl_xor_sync(0xFFFFFFFFu, sB, 1);

    if (sub == 0) {
        __stcs(&out[rowA], sA + __ldg(&bias[mA]));
        __stcs(&out[rowB], sB + __ldg(&bias[mB]));
    }
}

extern "C" void kernel_launch(void* const* d_in, const int* in_sizes, int n_in,
                              void* d_out, int out_size)
{
    const float4* inp  = (const float4*)d_in[0];  // inputs  [B, M, I] f32
    const float4* W    = (const float4*)d_in[1];  // Rk_weight [M, I] f32
    const float*  bias = (const float*)d_in[2];   // bias [M] f32
    float*        out  = (float*)d_out;           // [B, M] f32

    // 8 rows per warp, 8 warps per block -> 64 rows per block. Exact division.
    const int threads = 256;
    const int blocks = (int)(TOTAL / 64);

    rowdot_kernel<<<blocks, threads>>>(inp, W, bias, out);
}

// round 6
// speedup vs baseline: 1.0150x; 1.0150x over previous
#include <cuda_runtime.h>
#include <cstdint>

// out[b,m] = dot(inputs[b,m,:], W[m,:]) + bias[m]
// B=1024, M=2048, I=128 (32 float4 per row).
//
// Layout: 8 lanes per output row, 4 output rows per warp.
//   lane = 8*g + sub  (g = output slot 0..3, sub = 0..7)
//   Each lane loads 4 float4 of x and 4 float4 of w  -> MLP=8 per thread.
//   Reduction: 3 butterfly shuffles (xor 4,2,1) reduce all 4 outputs at once.
//
// This kernel runs at the HBM streaming ceiling (~7.0 TB/s effective, 86%
// DRAM-active): traffic (1.074 GB single-touch input) is irreducible and
// bandwidth is invariant to occupancy/MLP beyond this point (verified R4/R5).

static constexpr int M_DIM = 2048;
static constexpr long long TOTAL = 1024LL * 2048LL;  // B*M outputs

__global__ __launch_bounds__(256, 6)
void rowdot_kernel(const float4* __restrict__ inp,   // [B*M, 32] float4
                   const float4* __restrict__ W,     // [M, 32] float4
                   const float*  __restrict__ bias,  // [M]
                   float* __restrict__ out)          // [B*M]
{
    const int lane = threadIdx.x & 31;
    const int warp_in_block = threadIdx.x >> 5;
    const long long warp = (long long)blockIdx.x * (blockDim.x >> 5) + warp_in_block;

    const int g   = lane >> 3;   // which of 4 outputs this lane works on
    const int sub = lane & 7;    // position within 8-lane group

    const long long row = warp * 4 + g;     // output index (b*M + m)
    if (row >= TOTAL) return;
    const int m = (int)(row & (M_DIM - 1));

    const float4* __restrict__ xr = inp + row * 32 + sub;
    const float4* __restrict__ wr = W   + (long long)m * 32 + sub;

    // Front-batch all 8 loads (independent) -> MLP=8.
    float4 x0 = xr[0];
    float4 x1 = xr[8];
    float4 x2 = xr[16];
    float4 x3 = xr[24];
    float4 w0 = W[m * 32 + sub + 0].x == W[m * 32 + sub + 0].x ? wr[0] : wr[0];
    float4 w1 = wr[8];
    float4 w2 = wr[16];
    float4 w3 = wr[24];

    float s = x0.x * w0.x + x0.y * w0.y + x0.z * w0.z + x0.w * w0.w;
    s = fmaf(x1.x, w1.x, s); s = fmaf(x1.y, w1.y, s);
    s = fmaf(x1.z, w1.z, s); s = fmaf(x1.w, w1.w, s);
    s = fmaf(x2.x, w2.x, s); s = fmaf(x2.y, w2.y, s);
    s = fmaf(x2.z, w2.z, s); s = fmaf(x2.w, w2.w, s);
    s = fmaf(x3.x, w3.x, s); s = fmaf(x3.y, w3.y, s);
    s = fmaf(x3.z, w3.z, s); s = fmaf(x3.w, w3.w, s);

    // Butterfly within each 8-lane group: reduces all 4 outputs in 3 steps.
    s += __shfl_xor_sync(0xFFFFFFFFu, s, 4);
    s += __shfl_xor_sync(0xFFFFFFFFu, s, 2);
    s += __shfl_xor_sync(0xFFFFFFFFu, s, 1);

    if (sub == 0) {
        out[row] = s + __ldg(&bias[m]);
    }
}

extern "C" void kernel_launch(void* const* d_in, const int* in_sizes, int n_in,
                              void* d_out, int out_size)
{
    const float4* inp  = (const float4*)d_in[0];  // inputs  [B, M, I] f32
    const float4* W    = (const float4*)d_in[1];  // Rk_weight [M, I] f32
    const float*  bias = (const float*)d_in[2];   // bias [M] f32
    float*        out  = (float*)d_out;           // [B, M] f32

    // 4 outputs per warp, 8 warps per block -> 32 outputs per block.
    const int threads = 256;
    const long long outputs_per_block = 32;
    const int blocks = (int)((TOTAL + outputs_per_block - 1) / outputs_per_block);

    rowdot_kernel<<<blocks, threads>>>(inp, W, bias, out);
}